// round 16
// baseline (speedup 1.0000x reference)
#include <cuda_runtime.h>
#include <cuda_bf16.h>
#include <cstdint>

#define DEV_INLINE __device__ __forceinline__

#define NSPLIT 9      // attention KV splits
#define KSPLIT1 8     // gemm1 K splits
#define KSPLIT2 16    // gemm2 K splits
#define BN     128    // N tile
#define ALD    36     // A smem ld (words) -> 144B rows (16B aligned)
#define BLD    136    // B smem ld (words) -> 544B rows (16B aligned)
#define STAGE_A (64 * ALD)     // 2304 words
#define STAGE_B (32 * BLD)     // 4352 words
#define STAGE_W (STAGE_A + STAGE_B)   // 6656 words
#define STAGE_TX 24576         // payload bytes per stage (A 8192 + B 16384)
#define GEMM_SMEM (2 * STAGE_W * 4 + 32)   // stages + 4 mbarriers

// -------- device scratch (no allocations allowed) --------
__device__ float g_xq[64 * 4096];
__device__ float g_xk[64 * 1024];
__device__ float g_xv[64 * 1024];
__device__ float g_attn[64 * 4096];
__device__ float g_acc[64 * 6144];   // zero at load; rope self-cleans
__device__ float g_pm[4 * 32 * 16 * NSPLIT];
__device__ float g_pl[4 * 32 * 16 * NSPLIT];
__device__ float g_pacc[4 * 32 * 16 * NSPLIT * 128];

DEV_INLINE uint32_t f2tf(float x) {
    uint32_t r; asm("cvt.rna.tf32.f32 %0, %1;" : "=r"(r) : "f"(x)); return r;
}
DEV_INLINE uint32_t smem_u32(const void* p) {
    uint32_t a;
    asm("{ .reg .u64 t; cvta.to.shared.u64 t, %1; cvt.u32.u64 %0, t; }" : "=r"(a) : "l"(p));
    return a;
}
DEV_INLINE void mma_tf32(float* c, const uint32_t* a, const uint32_t* b) {
    asm volatile(
        "mma.sync.aligned.m16n8k8.row.col.f32.tf32.tf32.f32 "
        "{%0,%1,%2,%3}, {%4,%5,%6,%7}, {%8,%9}, {%0,%1,%2,%3};\n"
        : "+f"(c[0]), "+f"(c[1]), "+f"(c[2]), "+f"(c[3])
        : "r"(a[0]), "r"(a[1]), "r"(a[2]), "r"(a[3]), "r"(b[0]), "r"(b[1]));
}
DEV_INLINE void cp16(uint32_t dst, const float* src) {
    asm volatile("cp.async.cg.shared.global [%0], [%1], 16;\n" :: "r"(dst), "l"(src));
}
DEV_INLINE void red2(float* p, float a, float b) {
    asm volatile("red.global.add.v2.f32 [%0], {%1, %2};\n" :: "l"(p), "f"(a), "f"(b) : "memory");
}
DEV_INLINE void bulkcp(uint32_t dst, const float* src, int bytes, uint32_t mbar) {
    asm volatile(
        "cp.async.bulk.shared::cta.global.mbarrier::complete_tx::bytes [%0], [%1], %2, [%3];\n"
        :: "r"(dst), "l"(src), "r"(bytes), "r"(mbar) : "memory");
}
DEV_INLINE void mb_init(uint32_t mbar, uint32_t cnt) {
    asm volatile("mbarrier.init.shared.b64 [%0], %1;\n" :: "r"(mbar), "r"(cnt) : "memory");
}
DEV_INLINE void mb_expect(uint32_t mbar, uint32_t tx) {
    asm volatile("mbarrier.arrive.expect_tx.shared.b64 _, [%0], %1;\n" :: "r"(mbar), "r"(tx) : "memory");
}
DEV_INLINE void mb_arrive(uint32_t mbar) {
    asm volatile("mbarrier.arrive.shared.b64 _, [%0];\n" :: "r"(mbar) : "memory");
}
DEV_INLINE void mb_wait(uint32_t mbar, uint32_t parity) {
    asm volatile(
        "{\n\t.reg .pred P;\n"
        "WAIT_%=:\n\t"
        "mbarrier.try_wait.parity.acquire.cta.shared::cta.b64 P, [%0], %1, 0x989680;\n\t"
        "@P bra.uni DONE_%=;\n\t"
        "bra.uni WAIT_%=;\n"
        "DONE_%=:\n\t}"
        :: "r"(mbar), "r"(parity) : "memory");
}

// ============================================================
// TMA-bulk split-K GEMM: 64x128 tile, 288 threads
// (8 compute warps + 1 producer warp), 2-stage mbarrier pipeline,
// atomic epilogue. Bulk copies bypass the LDGSTS 8cyc/op LSU floor.
// ============================================================
template<int NTOT, bool AFA, int KSPL>
__global__ __launch_bounds__(288, 2) void gemm_tma(
    const float* __restrict__ Ain, const float* __restrict__ W0,
    const float* __restrict__ W1, const float* __restrict__ W2,
    float* __restrict__ dst) {
    constexpr int KCH = 4096 / KSPL;
    constexpr int NITER = KCH / 32;
    extern __shared__ float sm[];
    uint32_t mb = smem_u32(sm + 2 * STAGE_W);   // full0, full1, empty0, empty1 (8B each)

    const int ntile = blockIdx.x, split = blockIdx.y;
    const int n0 = ntile * BN;
    const float* A = AFA ? (const float*)g_attn : Ain;
    const float* Bp; int ldn, nb;
    if (NTOT == 4096) { Bp = W0; ldn = 4096; nb = n0; }
    else {
        if (n0 < 4096)      { Bp = W0; ldn = 4096; nb = n0; }
        else if (n0 < 5120) { Bp = W1; ldn = 1024; nb = n0 - 4096; }
        else                { Bp = W2; ldn = 1024; nb = n0 - 5120; }
    }
    const int k0 = split * KCH;
    const int tid = threadIdx.x;
    const uint32_t sbase = smem_u32(sm);

    if (tid == 0) {
        mb_init(mb, 1);  mb_init(mb + 8, 1);     // full[2]: 1 expect_tx arrive
        mb_init(mb + 16, 1); mb_init(mb + 24, 1); // empty[2]: 1 consumer arrive
    }
    __syncthreads();

    const int w = tid >> 5;

    if (w == 8) {
        // -------- producer warp --------
        const int lane = tid & 31;
        for (int it = 0; it < NITER; it++) {
            const int buf = it & 1;
            if (it >= 2) mb_wait(mb + 16 + buf * 8, ((it >> 1) - 1) & 1);
            if (lane == 0) mb_expect(mb + buf * 8, STAGE_TX);
            __syncwarp();
            const int kc = k0 + it * 32;
            uint32_t as_ = sbase + buf * STAGE_W * 4;
            uint32_t bs_ = as_ + STAGE_A * 4;
            // A: 64 rows x 128B
            bulkcp(as_ + lane * ALD * 4, A + lane * 4096 + kc, 128, mb + buf * 8);
            bulkcp(as_ + (lane + 32) * ALD * 4, A + (lane + 32) * 4096 + kc, 128, mb + buf * 8);
            // B: 32 rows x 512B
            bulkcp(bs_ + lane * BLD * 4, Bp + (kc + lane) * ldn + nb, 512, mb + buf * 8);
        }
        return;
    }

    // -------- consumer warps 0..7 --------
    const int lane = tid & 31, g = lane >> 2, tg = lane & 3;
    const int wm = (w & 1) * 32;
    const int wn = (w >> 1) * 32;

    float acc[2][4][4];
#pragma unroll
    for (int mf = 0; mf < 2; mf++)
#pragma unroll
        for (int nt = 0; nt < 4; nt++)
#pragma unroll
            for (int j = 0; j < 4; j++) acc[mf][nt][j] = 0.f;

    for (int it = 0; it < NITER; it++) {
        const int buf = it & 1;
        mb_wait(mb + buf * 8, (it >> 1) & 1);
        const float* As = sm + buf * STAGE_W;
        const float* Bs = As + STAGE_A;
#pragma unroll
        for (int ks = 0; ks < 4; ks++) {
            const int kk = ks * 8;
            uint32_t a[2][4];
#pragma unroll
            for (int mf = 0; mf < 2; mf++) {
                const int r0 = wm + mf * 16;
                a[mf][0] = f2tf(As[(r0 + g) * ALD + kk + tg]);
                a[mf][1] = f2tf(As[(r0 + g + 8) * ALD + kk + tg]);
                a[mf][2] = f2tf(As[(r0 + g) * ALD + kk + tg + 4]);
                a[mf][3] = f2tf(As[(r0 + g + 8) * ALD + kk + tg + 4]);
            }
#pragma unroll
            for (int nt = 0; nt < 4; nt++) {
                uint32_t bb[2];
                bb[0] = f2tf(Bs[(kk + tg) * BLD + wn + nt * 8 + g]);
                bb[1] = f2tf(Bs[(kk + tg + 4) * BLD + wn + nt * 8 + g]);
                mma_tf32(acc[0][nt], a[0], bb);
                mma_tf32(acc[1][nt], a[1], bb);
            }
        }
        asm volatile("bar.sync 1, 256;\n" ::: "memory");   // consumers done with buf
        if (tid == 0) mb_arrive(mb + 16 + buf * 8);
    }

    // atomic split-K reduction epilogue
#pragma unroll
    for (int mf = 0; mf < 2; mf++) {
        const int rA = wm + mf * 16 + g, rB = rA + 8;
#pragma unroll
        for (int nt = 0; nt < 4; nt++) {
            int col = n0 + wn + nt * 8 + tg * 2;
            red2(dst + rA * NTOT + col, acc[mf][nt][0], acc[mf][nt][1]);
            red2(dst + rB * NTOT + col, acc[mf][nt][2], acc[mf][nt][3]);
        }
    }
}

// ============================================================
// RoPE pass: read g_acc, rotate, scatter; re-zero g_acc; zero out.
// ============================================================
__global__ __launch_bounds__(256) void rope_kernel(
    const float* __restrict__ fc, const float* __restrict__ fs,
    float4* __restrict__ out) {
    int idx = blockIdx.x * 256 + threadIdx.x;       // 98304 threads
    if (idx < 65536) out[idx] = make_float4(0.f, 0.f, 0.f, 0.f);
    int r = idx / 1536, q4 = idx % 1536;
    int n = q4 * 4;
    float4 v = *(const float4*)(g_acc + r * 6144 + n);
    int srow = r & 15;
    if (n < 4096) {
        int i2 = (n & 127) >> 1;
        float c0 = fc[srow * 64 + i2],     s0 = fs[srow * 64 + i2];
        float c1 = fc[srow * 64 + i2 + 1], s1 = fs[srow * 64 + i2 + 1];
        float4 o;
        o.x = v.x * c0 - v.y * s0; o.y = v.x * s0 + v.y * c0;
        o.z = v.z * c1 - v.w * s1; o.w = v.z * s1 + v.w * c1;
        *(float4*)(g_xq + r * 4096 + n) = o;
    } else if (n < 5120) {
        int nk = n - 4096; int i2 = (nk & 127) >> 1;
        float c0 = fc[srow * 64 + i2],     s0 = fs[srow * 64 + i2];
        float c1 = fc[srow * 64 + i2 + 1], s1 = fs[srow * 64 + i2 + 1];
        float4 o;
        o.x = v.x * c0 - v.y * s0; o.y = v.x * s0 + v.y * c0;
        o.z = v.z * c1 - v.w * s1; o.w = v.z * s1 + v.w * c1;
        *(float4*)(g_xk + r * 1024 + nk) = o;
    } else {
        int nv = n - 5120;
        *(float4*)(g_xv + r * 1024 + nv) = v;
    }
    *(float4*)(g_acc + r * 6144 + n) = make_float4(0.f, 0.f, 0.f, 0.f);
}

// ============================================================
// split-KV flash attention (R14/R8 form — proven fastest)
// ============================================================
#define QLD 132
#define KLD 132
#define VLD 136
#define PLD 36
#define AQ_W  (64 * QLD)
#define AK_W  (32 * KLD)
#define AV_W  (32 * VLD)
#define AP_W  (64 * PLD)
#define ATTN_SMEM ((AQ_W + 2 * AK_W + 2 * AV_W + AP_W) * 4)

__global__ __launch_bounds__(128) void attn_kernel(
    const float* __restrict__ cache_k, const float* __restrict__ cache_v) {
    extern __shared__ float smf[];
    uint32_t* Qs = (uint32_t*)smf;
    float* Kb = smf + AQ_W;
    float* Vb = Kb + 2 * AK_W;
    uint32_t* Ps = (uint32_t*)(Vb + 2 * AV_W);

    const int split = blockIdx.x, kvh = blockIdx.y, b = blockIdx.z;
    const int tid = threadIdx.x, w = tid >> 5, lane = tid & 31;
    const int g = lane >> 2, tg = lane & 3;
    const uint32_t sbase = smem_u32(smf);
    const uint32_t kbase = sbase + AQ_W * 4;
    const uint32_t vbase = kbase + 2 * AK_W * 4;
    const int nch = (split < 8) ? 8 : 1;

    auto issue = [&](int ch, int buf) {
        uint32_t kb = kbase + buf * AK_W * 4;
        uint32_t vb = vbase + buf * AV_W * 4;
        if (split < 8) {
#pragma unroll
            for (int i = 0; i < 8; i++) {
                int idx = tid + i * 128; int jk = idx >> 5, c = (idx & 31) * 4;
                int j = split * 256 + ch * 32 + jk;
                int off = ((b * 4096 + j) * 8 + kvh) * 128 + c;
                cp16(kb + (jk * KLD + c) * 4, cache_k + off);
                cp16(vb + (jk * VLD + c) * 4, cache_v + off);
            }
        } else {
#pragma unroll
            for (int i = 0; i < 4; i++) {
                int idx = tid + i * 128; int jk = idx >> 5, c = (idx & 31) * 4;
                int off = (b * 16 + jk) * 1024 + kvh * 128 + c;
                cp16(kb + (jk * KLD + c) * 4, g_xk + off);
                cp16(vb + (jk * VLD + c) * 4, g_xv + off);
            }
        }
        asm volatile("cp.async.commit_group;\n");
    };

    if (split == 8) {
#pragma unroll
        for (int i = 0; i < 16; i++) {
            int idx = tid + i * 128; int jk = 16 + (idx >> 5), c = idx & 31;
            Kb[jk * KLD + c * 4] = 0.f; Kb[jk * KLD + c * 4 + 1] = 0.f;
            Kb[jk * KLD + c * 4 + 2] = 0.f; Kb[jk * KLD + c * 4 + 3] = 0.f;
            Vb[jk * VLD + c * 4] = 0.f; Vb[jk * VLD + c * 4 + 1] = 0.f;
            Vb[jk * VLD + c * 4 + 2] = 0.f; Vb[jk * VLD + c * 4 + 3] = 0.f;
        }
    }
    issue(0, 0);

#pragma unroll
    for (int i = 0; i < 16; i++) {
        int idx = tid + i * 128; int r = idx >> 5, c = (idx & 31) * 4;
        int hig = r >> 4, s = r & 15;
        float4 v = *(const float4*)(g_xq + (b * 16 + s) * 4096 + (kvh * 4 + hig) * 128 + c);
        uint32_t* q = &Qs[r * QLD + c];
        q[0] = f2tf(v.x); q[1] = f2tf(v.y); q[2] = f2tf(v.z); q[3] = f2tf(v.w);
    }

    float acc[16][4];
#pragma unroll
    for (int i = 0; i < 16; i++)
#pragma unroll
        for (int j = 0; j < 4; j++) acc[i][j] = 0.f;
    float m0 = -1e30f, m1 = -1e30f, l0 = 0.f, l1 = 0.f;
    const float scale = 0.08838834764831845f;

    for (int ch = 0; ch < nch; ch++) {
        if (ch + 1 < nch) {
            issue(ch + 1, (ch + 1) & 1);
            asm volatile("cp.async.wait_group 1;\n");
        } else {
            asm volatile("cp.async.wait_group 0;\n");
        }
        __syncthreads();
        const float* Kc = Kb + (ch & 1) * AK_W;
        const float* Vc = Vb + (ch & 1) * AV_W;

        float sc[4][4];
#pragma unroll
        for (int i = 0; i < 4; i++)
#pragma unroll
            for (int j = 0; j < 4; j++) sc[i][j] = 0.f;
#pragma unroll
        for (int ks = 0; ks < 16; ks++) {
            uint32_t a[4];
            a[0] = Qs[(w * 16 + g) * QLD + ks * 8 + tg];
            a[1] = Qs[(w * 16 + g + 8) * QLD + ks * 8 + tg];
            a[2] = Qs[(w * 16 + g) * QLD + ks * 8 + tg + 4];
            a[3] = Qs[(w * 16 + g + 8) * QLD + ks * 8 + tg + 4];
#pragma unroll
            for (int nt = 0; nt < 4; nt++) {
                uint32_t bb[2];
                bb[0] = f2tf(Kc[(nt * 8 + g) * KLD + ks * 8 + tg]);
                bb[1] = f2tf(Kc[(nt * 8 + g) * KLD + ks * 8 + tg + 4]);
                mma_tf32(sc[nt], a, bb);
            }
        }

        float mx0 = -1e30f, mx1 = -1e30f;
#pragma unroll
        for (int nt = 0; nt < 4; nt++) {
#pragma unroll
            for (int r = 0; r < 4; r++) {
                float v = sc[nt][r] * scale;
                if (split == 8) {
                    int key = nt * 8 + tg * 2 + (r & 1);
                    if (key >= 16) v = -1e30f;
                }
                sc[nt][r] = v;
            }
            mx0 = fmaxf(mx0, fmaxf(sc[nt][0], sc[nt][1]));
            mx1 = fmaxf(mx1, fmaxf(sc[nt][2], sc[nt][3]));
        }
        mx0 = fmaxf(mx0, __shfl_xor_sync(0xffffffffu, mx0, 1));
        mx0 = fmaxf(mx0, __shfl_xor_sync(0xffffffffu, mx0, 2));
        mx1 = fmaxf(mx1, __shfl_xor_sync(0xffffffffu, mx1, 1));
        mx1 = fmaxf(mx1, __shfl_xor_sync(0xffffffffu, mx1, 2));
        float nm0 = fmaxf(m0, mx0), nm1 = fmaxf(m1, mx1);
        float f0 = __expf(m0 - nm0), f1 = __expf(m1 - nm1);
        float s0 = 0.f, s1 = 0.f;
#pragma unroll
        for (int nt = 0; nt < 4; nt++) {
            float p0 = __expf(sc[nt][0] - nm0), p1 = __expf(sc[nt][1] - nm0);
            float p2 = __expf(sc[nt][2] - nm1), p3 = __expf(sc[nt][3] - nm1);
            s0 += p0 + p1; s1 += p2 + p3;
            uint32_t* pr  = &Ps[(w * 16 + g) * PLD + nt * 8 + tg * 2];
            pr[0] = f2tf(p0); pr[1] = f2tf(p1);
            uint32_t* pr2 = &Ps[(w * 16 + g + 8) * PLD + nt * 8 + tg * 2];
            pr2[0] = f2tf(p2); pr2[1] = f2tf(p3);
        }
        s0 += __shfl_xor_sync(0xffffffffu, s0, 1);
        s0 += __shfl_xor_sync(0xffffffffu, s0, 2);
        s1 += __shfl_xor_sync(0xffffffffu, s1, 1);
        s1 += __shfl_xor_sync(0xffffffffu, s1, 2);
        l0 = l0 * f0 + s0; l1 = l1 * f1 + s1;
        m0 = nm0; m1 = nm1;
#pragma unroll
        for (int nt = 0; nt < 16; nt++) {
            acc[nt][0] *= f0; acc[nt][1] *= f0;
            acc[nt][2] *= f1; acc[nt][3] *= f1;
        }
        __syncwarp();

#pragma unroll
        for (int k2 = 0; k2 < 4; k2++) {
            uint32_t a[4];
            a[0] = Ps[(w * 16 + g) * PLD + k2 * 8 + tg];
            a[1] = Ps[(w * 16 + g + 8) * PLD + k2 * 8 + tg];
            a[2] = Ps[(w * 16 + g) * PLD + k2 * 8 + tg + 4];
            a[3] = Ps[(w * 16 + g + 8) * PLD + k2 * 8 + tg + 4];
#pragma unroll
            for (int nt = 0; nt < 16; nt++) {
                uint32_t bb[2];
                bb[0] = f2tf(Vc[(k2 * 8 + tg) * VLD + nt * 8 + g]);
                bb[1] = f2tf(Vc[(k2 * 8 + tg + 4) * VLD + nt * 8 + g]);
                mma_tf32(acc[nt], a, bb);
            }
        }
        __syncthreads();
    }

    const int h = kvh * 4 + w;
    const int baseA = ((b * 32 + h) * 16 + g) * NSPLIT + split;
    const int baseB = ((b * 32 + h) * 16 + g + 8) * NSPLIT + split;
    if (tg == 0) {
        g_pm[baseA] = m0; g_pl[baseA] = l0;
        g_pm[baseB] = m1; g_pl[baseB] = l1;
    }
#pragma unroll
    for (int nt = 0; nt < 16; nt++) {
        int col = nt * 8 + tg * 2;
        g_pacc[baseA * 128 + col]     = acc[nt][0];
        g_pacc[baseA * 128 + col + 1] = acc[nt][1];
        g_pacc[baseB * 128 + col]     = acc[nt][2];
        g_pacc[baseB * 128 + col + 1] = acc[nt][3];
    }
}

// ============================================================
// combine: 8 rows per block, float4 loads
// ============================================================
__global__ __launch_bounds__(256) void combine_kernel() {
    int bhs = blockIdx.x * 8 + (threadIdx.x >> 5);
    int lane = threadIdx.x & 31;
    int base = bhs * NSPLIT;
    float m = -1e30f;
#pragma unroll
    for (int i = 0; i < NSPLIT; i++) m = fmaxf(m, g_pm[base + i]);
    float L = 0.f;
    float4 o = make_float4(0.f, 0.f, 0.f, 0.f);
#pragma unroll
    for (int i = 0; i < NSPLIT; i++) {
        float e = __expf(g_pm[base + i] - m);
        L += g_pl[base + i] * e;
        float4 v = *(const float4*)(g_pacc + (base + i) * 128 + lane * 4);
        o.x += v.x * e; o.y += v.y * e; o.z += v.z * e; o.w += v.w * e;
    }
    float inv = 1.f / L;
    int b = bhs >> 9, h = (bhs >> 4) & 31, s = bhs & 15;
    float4 r = make_float4(o.x * inv, o.y * inv, o.z * inv, o.w * inv);
    *(float4*)(g_attn + (b * 16 + s) * 4096 + h * 128 + lane * 4) = r;
}

// ============================================================
extern "C" void kernel_launch(void* const* d_in, const int* in_sizes, int n_in,
                              void* d_out, int out_size) {
    const float* x  = (const float*)d_in[0];
    const float* fc = (const float*)d_in[1];
    const float* fs = (const float*)d_in[2];
    const float* ck = (const float*)d_in[3];
    const float* cv = (const float*)d_in[4];
    const float* Wq = (const float*)d_in[5];
    const float* Wk = (const float*)d_in[6];
    const float* Wv = (const float*)d_in[7];
    const float* Wo = (const float*)d_in[8];
    float* out = (float*)d_out;

    cudaFuncSetAttribute((const void*)gemm_tma<6144, false, KSPLIT1>, cudaFuncAttributeMaxDynamicSharedMemorySize, GEMM_SMEM);
    cudaFuncSetAttribute((const void*)gemm_tma<4096, true, KSPLIT2>,  cudaFuncAttributeMaxDynamicSharedMemorySize, GEMM_SMEM);
    cudaFuncSetAttribute(attn_kernel, cudaFuncAttributeMaxDynamicSharedMemorySize, ATTN_SMEM);

    float* acc_ptr;
    cudaGetSymbolAddress((void**)&acc_ptr, g_acc);

    gemm_tma<6144, false, KSPLIT1><<<dim3(48, KSPLIT1), 288, GEMM_SMEM>>>(x, Wq, Wk, Wv, acc_ptr);
    rope_kernel<<<384, 256>>>(fc, fs, (float4*)out);
    attn_kernel<<<dim3(NSPLIT, 8, 4), 128, ATTN_SMEM>>>(ck, cv);
    combine_kernel<<<256, 256>>>();
    gemm_tma<4096, true, KSPLIT2><<<dim3(32, KSPLIT2), 288, GEMM_SMEM>>>(nullptr, Wo, nullptr, nullptr, out);
}

// round 17
// speedup vs baseline: 2.0396x; 2.0396x over previous
#include <cuda_runtime.h>
#include <cuda_bf16.h>
#include <cstdint>

#define DEV_INLINE __device__ __forceinline__

#define NSPLIT 9      // attention KV splits
#define KSPLIT1 8     // gemm1 K splits (measured best)
#define KSPLIT2 16    // gemm2 K splits
#define BN     128    // N tile
#define ALD    36     // A smem ld (words)
#define BLD    136    // B smem ld (words)
#define STAGE_A (64 * ALD)     // 2304 words
#define STAGE_B (32 * BLD)     // 4352 words
#define STAGE_W (STAGE_A + STAGE_B)   // 6656 words = 26 KB
#define NSTAGE 2
#define GEMM_SMEM (NSTAGE * STAGE_W * 4)   // 53248 B

// -------- device scratch (no allocations allowed) --------
__device__ float g_xq[64 * 4096];
__device__ float g_xk[64 * 1024];
__device__ float g_xv[64 * 1024];
__device__ float g_attn[64 * 4096];
__device__ float g_acc[64 * 6144];   // zero-init at load; rope self-cleans
__device__ float g_pm[4 * 32 * 16 * NSPLIT];
__device__ float g_pl[4 * 32 * 16 * NSPLIT];
__device__ float g_pacc[4 * 32 * 16 * NSPLIT * 128];

DEV_INLINE uint32_t f2tf(float x) {
    uint32_t r; asm("cvt.rna.tf32.f32 %0, %1;" : "=r"(r) : "f"(x)); return r;
}
DEV_INLINE uint32_t smem_u32(const void* p) {
    uint32_t a;
    asm("{ .reg .u64 t; cvta.to.shared.u64 t, %1; cvt.u32.u64 %0, t; }" : "=r"(a) : "l"(p));
    return a;
}
DEV_INLINE void mma_tf32(float* c, const uint32_t* a, const uint32_t* b) {
    asm volatile(
        "mma.sync.aligned.m16n8k8.row.col.f32.tf32.tf32.f32 "
        "{%0,%1,%2,%3}, {%4,%5,%6,%7}, {%8,%9}, {%0,%1,%2,%3};\n"
        : "+f"(c[0]), "+f"(c[1]), "+f"(c[2]), "+f"(c[3])
        : "r"(a[0]), "r"(a[1]), "r"(a[2]), "r"(a[3]), "r"(b[0]), "r"(b[1]));
}
DEV_INLINE void cp16(uint32_t dst, const float* src) {
    asm volatile("cp.async.cg.shared.global [%0], [%1], 16;\n" :: "r"(dst), "l"(src));
}
DEV_INLINE void red2(float* p, float a, float b) {
    asm volatile("red.global.add.v2.f32 [%0], {%1, %2};\n" :: "l"(p), "f"(a), "f"(b) : "memory");
}

// ============================================================
// Split-K GEMM: 64 x 128 block tile, 256 threads (2M x 4N warps),
// 2-stage cp.async, atomic epilogue into dst. (256,3) reg budget.
// (exact R14 form — 97.0us baseline)
// ============================================================
template<int NTOT, bool AFA, int KSPL>
__global__ __launch_bounds__(256, 3) void gemm_k(
    const float* __restrict__ Ain, const float* __restrict__ W0,
    const float* __restrict__ W1, const float* __restrict__ W2,
    float* __restrict__ dst) {
    constexpr int KCH = 4096 / KSPL;
    constexpr int NITER = KCH / 32;
    extern __shared__ float sm[];
    const int ntile = blockIdx.x, split = blockIdx.y;
    const int n0 = ntile * BN;
    const float* A = AFA ? (const float*)g_attn : Ain;
    const float* Bp; int ldn, nb;
    if (NTOT == 4096) { Bp = W0; ldn = 4096; nb = n0; }
    else {
        if (n0 < 4096)      { Bp = W0; ldn = 4096; nb = n0; }
        else if (n0 < 5120) { Bp = W1; ldn = 1024; nb = n0 - 4096; }
        else                { Bp = W2; ldn = 1024; nb = n0 - 5120; }
    }
    const int k0 = split * KCH;
    const int tid = threadIdx.x;
    const uint32_t sbase = smem_u32(sm);

    auto issue = [&](int it, int buf) {
        const int kc = k0 + it * 32;
        uint32_t as_ = sbase + buf * STAGE_W * 4;
        uint32_t bs_ = as_ + STAGE_A * 4;
#pragma unroll
        for (int i = 0; i < 2; i++) {                 // A: 64x32 = 512 float4
            int idx = tid + i * 256; int r = idx >> 3, c = (idx & 7) * 4;
            cp16(as_ + (r * ALD + c) * 4, A + r * 4096 + kc + c);
        }
#pragma unroll
        for (int i = 0; i < 4; i++) {                 // B: 32x128 = 1024 float4
            int idx = tid + i * 256; int r = idx >> 5, c = (idx & 31) * 4;
            cp16(bs_ + (r * BLD + c) * 4, Bp + (kc + r) * ldn + nb + c);
        }
        asm volatile("cp.async.commit_group;\n");
    };

    const int w = tid >> 5, lane = tid & 31, g = lane >> 2, tg = lane & 3;
    const int wm = (w & 1) * 32;
    const int wn = (w >> 1) * 32;

    float acc[2][4][4];
#pragma unroll
    for (int mf = 0; mf < 2; mf++)
#pragma unroll
        for (int nt = 0; nt < 4; nt++)
#pragma unroll
            for (int j = 0; j < 4; j++) acc[mf][nt][j] = 0.f;

    issue(0, 0);

    for (int it = 0; it < NITER; it++) {
        if (it + 1 < NITER) {
            issue(it + 1, (it + 1) & 1);
            asm volatile("cp.async.wait_group 1;\n");
        } else {
            asm volatile("cp.async.wait_group 0;\n");
        }
        __syncthreads();
        const float* As = sm + (it & 1) * STAGE_W;
        const float* Bs = As + STAGE_A;
#pragma unroll
        for (int ks = 0; ks < 4; ks++) {
            const int kk = ks * 8;
            uint32_t a[2][4];
#pragma unroll
            for (int mf = 0; mf < 2; mf++) {
                const int r0 = wm + mf * 16;
                a[mf][0] = f2tf(As[(r0 + g) * ALD + kk + tg]);
                a[mf][1] = f2tf(As[(r0 + g + 8) * ALD + kk + tg]);
                a[mf][2] = f2tf(As[(r0 + g) * ALD + kk + tg + 4]);
                a[mf][3] = f2tf(As[(r0 + g + 8) * ALD + kk + tg + 4]);
            }
#pragma unroll
            for (int nt = 0; nt < 4; nt++) {
                uint32_t bb[2];
                bb[0] = f2tf(Bs[(kk + tg) * BLD + wn + nt * 8 + g]);
                bb[1] = f2tf(Bs[(kk + tg + 4) * BLD + wn + nt * 8 + g]);
                mma_tf32(acc[0][nt], a[0], bb);
                mma_tf32(acc[1][nt], a[1], bb);
            }
        }
        __syncthreads();
    }

    // atomic split-K reduction epilogue
#pragma unroll
    for (int mf = 0; mf < 2; mf++) {
        const int rA = wm + mf * 16 + g, rB = rA + 8;
#pragma unroll
        for (int nt = 0; nt < 4; nt++) {
            int col = n0 + wn + nt * 8 + tg * 2;
            red2(dst + rA * NTOT + col, acc[mf][nt][0], acc[mf][nt][1]);
            red2(dst + rB * NTOT + col, acc[mf][nt][2], acc[mf][nt][3]);
        }
    }
}

// ============================================================
// RoPE pass: read g_acc, rotate, scatter; re-zero g_acc; zero out.
// ============================================================
__global__ __launch_bounds__(256) void rope_kernel(
    const float* __restrict__ fc, const float* __restrict__ fs,
    float4* __restrict__ out) {
    int idx = blockIdx.x * 256 + threadIdx.x;       // 98304 threads
    if (idx < 65536) out[idx] = make_float4(0.f, 0.f, 0.f, 0.f);
    int r = idx / 1536, q4 = idx % 1536;
    int n = q4 * 4;
    float4 v = *(const float4*)(g_acc + r * 6144 + n);
    int srow = r & 15;
    if (n < 4096) {
        int i2 = (n & 127) >> 1;
        float c0 = fc[srow * 64 + i2],     s0 = fs[srow * 64 + i2];
        float c1 = fc[srow * 64 + i2 + 1], s1 = fs[srow * 64 + i2 + 1];
        float4 o;
        o.x = v.x * c0 - v.y * s0; o.y = v.x * s0 + v.y * c0;
        o.z = v.z * c1 - v.w * s1; o.w = v.z * s1 + v.w * c1;
        *(float4*)(g_xq + r * 4096 + n) = o;
    } else if (n < 5120) {
        int nk = n - 4096; int i2 = (nk & 127) >> 1;
        float c0 = fc[srow * 64 + i2],     s0 = fs[srow * 64 + i2];
        float c1 = fc[srow * 64 + i2 + 1], s1 = fs[srow * 64 + i2 + 1];
        float4 o;
        o.x = v.x * c0 - v.y * s0; o.y = v.x * s0 + v.y * c0;
        o.z = v.z * c1 - v.w * s1; o.w = v.z * s1 + v.w * c1;
        *(float4*)(g_xk + r * 1024 + nk) = o;
    } else {
        int nv = n - 5120;
        *(float4*)(g_xv + r * 1024 + nv) = v;
    }
    *(float4*)(g_acc + r * 6144 + n) = make_float4(0.f, 0.f, 0.f, 0.f);
}

// ============================================================
// split-KV flash attention (R8/R14 form — proven fastest)
// ============================================================
#define QLD 132
#define KLD 132
#define VLD 136
#define PLD 36
#define AQ_W  (64 * QLD)
#define AK_W  (32 * KLD)
#define AV_W  (32 * VLD)
#define AP_W  (64 * PLD)
#define ATTN_SMEM ((AQ_W + 2 * AK_W + 2 * AV_W + AP_W) * 4)

__global__ __launch_bounds__(128) void attn_kernel(
    const float* __restrict__ cache_k, const float* __restrict__ cache_v) {
    extern __shared__ float smf[];
    uint32_t* Qs = (uint32_t*)smf;
    float* Kb = smf + AQ_W;
    float* Vb = Kb + 2 * AK_W;
    uint32_t* Ps = (uint32_t*)(Vb + 2 * AV_W);

    const int split = blockIdx.x, kvh = blockIdx.y, b = blockIdx.z;
    const int tid = threadIdx.x, w = tid >> 5, lane = tid & 31;
    const int g = lane >> 2, tg = lane & 3;
    const uint32_t sbase = smem_u32(smf);
    const uint32_t kbase = sbase + AQ_W * 4;
    const uint32_t vbase = kbase + 2 * AK_W * 4;
    const int nch = (split < 8) ? 8 : 1;

    auto issue = [&](int ch, int buf) {
        uint32_t kb = kbase + buf * AK_W * 4;
        uint32_t vb = vbase + buf * AV_W * 4;
        if (split < 8) {
#pragma unroll
            for (int i = 0; i < 8; i++) {
                int idx = tid + i * 128; int jk = idx >> 5, c = (idx & 31) * 4;
                int j = split * 256 + ch * 32 + jk;
                int off = ((b * 4096 + j) * 8 + kvh) * 128 + c;
                cp16(kb + (jk * KLD + c) * 4, cache_k + off);
                cp16(vb + (jk * VLD + c) * 4, cache_v + off);
            }
        } else {
#pragma unroll
            for (int i = 0; i < 4; i++) {
                int idx = tid + i * 128; int jk = idx >> 5, c = (idx & 31) * 4;
                int off = (b * 16 + jk) * 1024 + kvh * 128 + c;
                cp16(kb + (jk * KLD + c) * 4, g_xk + off);
                cp16(vb + (jk * VLD + c) * 4, g_xv + off);
            }
        }
        asm volatile("cp.async.commit_group;\n");
    };

    if (split == 8) {
#pragma unroll
        for (int i = 0; i < 16; i++) {
            int idx = tid + i * 128; int jk = 16 + (idx >> 5), c = idx & 31;
            Kb[jk * KLD + c * 4] = 0.f; Kb[jk * KLD + c * 4 + 1] = 0.f;
            Kb[jk * KLD + c * 4 + 2] = 0.f; Kb[jk * KLD + c * 4 + 3] = 0.f;
            Vb[jk * VLD + c * 4] = 0.f; Vb[jk * VLD + c * 4 + 1] = 0.f;
            Vb[jk * VLD + c * 4 + 2] = 0.f; Vb[jk * VLD + c * 4 + 3] = 0.f;
        }
    }
    issue(0, 0);

#pragma unroll
    for (int i = 0; i < 16; i++) {
        int idx = tid + i * 128; int r = idx >> 5, c = (idx & 31) * 4;
        int hig = r >> 4, s = r & 15;
        float4 v = *(const float4*)(g_xq + (b * 16 + s) * 4096 + (kvh * 4 + hig) * 128 + c);
        uint32_t* q = &Qs[r * QLD + c];
        q[0] = f2tf(v.x); q[1] = f2tf(v.y); q[2] = f2tf(v.z); q[3] = f2tf(v.w);
    }

    float acc[16][4];
#pragma unroll
    for (int i = 0; i < 16; i++)
#pragma unroll
        for (int j = 0; j < 4; j++) acc[i][j] = 0.f;
    float m0 = -1e30f, m1 = -1e30f, l0 = 0.f, l1 = 0.f;
    const float scale = 0.08838834764831845f;

    for (int ch = 0; ch < nch; ch++) {
        if (ch + 1 < nch) {
            issue(ch + 1, (ch + 1) & 1);
            asm volatile("cp.async.wait_group 1;\n");
        } else {
            asm volatile("cp.async.wait_group 0;\n");
        }
        __syncthreads();
        const float* Kc = Kb + (ch & 1) * AK_W;
        const float* Vc = Vb + (ch & 1) * AV_W;

        float sc[4][4];
#pragma unroll
        for (int i = 0; i < 4; i++)
#pragma unroll
            for (int j = 0; j < 4; j++) sc[i][j] = 0.f;
#pragma unroll
        for (int ks = 0; ks < 16; ks++) {
            uint32_t a[4];
            a[0] = Qs[(w * 16 + g) * QLD + ks * 8 + tg];
            a[1] = Qs[(w * 16 + g + 8) * QLD + ks * 8 + tg];
            a[2] = Qs[(w * 16 + g) * QLD + ks * 8 + tg + 4];
            a[3] = Qs[(w * 16 + g + 8) * QLD + ks * 8 + tg + 4];
#pragma unroll
            for (int nt = 0; nt < 4; nt++) {
                uint32_t bb[2];
                bb[0] = f2tf(Kc[(nt * 8 + g) * KLD + ks * 8 + tg]);
                bb[1] = f2tf(Kc[(nt * 8 + g) * KLD + ks * 8 + tg + 4]);
                mma_tf32(sc[nt], a, bb);
            }
        }

        float mx0 = -1e30f, mx1 = -1e30f;
#pragma unroll
        for (int nt = 0; nt < 4; nt++) {
#pragma unroll
            for (int r = 0; r < 4; r++) {
                float v = sc[nt][r] * scale;
                if (split == 8) {
                    int key = nt * 8 + tg * 2 + (r & 1);
                    if (key >= 16) v = -1e30f;
                }
                sc[nt][r] = v;
            }
            mx0 = fmaxf(mx0, fmaxf(sc[nt][0], sc[nt][1]));
            mx1 = fmaxf(mx1, fmaxf(sc[nt][2], sc[nt][3]));
        }
        mx0 = fmaxf(mx0, __shfl_xor_sync(0xffffffffu, mx0, 1));
        mx0 = fmaxf(mx0, __shfl_xor_sync(0xffffffffu, mx0, 2));
        mx1 = fmaxf(mx1, __shfl_xor_sync(0xffffffffu, mx1, 1));
        mx1 = fmaxf(mx1, __shfl_xor_sync(0xffffffffu, mx1, 2));
        float nm0 = fmaxf(m0, mx0), nm1 = fmaxf(m1, mx1);
        float f0 = __expf(m0 - nm0), f1 = __expf(m1 - nm1);
        float s0 = 0.f, s1 = 0.f;
#pragma unroll
        for (int nt = 0; nt < 4; nt++) {
            float p0 = __expf(sc[nt][0] - nm0), p1 = __expf(sc[nt][1] - nm0);
            float p2 = __expf(sc[nt][2] - nm1), p3 = __expf(sc[nt][3] - nm1);
            s0 += p0 + p1; s1 += p2 + p3;
            uint32_t* pr  = &Ps[(w * 16 + g) * PLD + nt * 8 + tg * 2];
            pr[0] = f2tf(p0); pr[1] = f2tf(p1);
            uint32_t* pr2 = &Ps[(w * 16 + g + 8) * PLD + nt * 8 + tg * 2];
            pr2[0] = f2tf(p2); pr2[1] = f2tf(p3);
        }
        s0 += __shfl_xor_sync(0xffffffffu, s0, 1);
        s0 += __shfl_xor_sync(0xffffffffu, s0, 2);
        s1 += __shfl_xor_sync(0xffffffffu, s1, 1);
        s1 += __shfl_xor_sync(0xffffffffu, s1, 2);
        l0 = l0 * f0 + s0; l1 = l1 * f1 + s1;
        m0 = nm0; m1 = nm1;
#pragma unroll
        for (int nt = 0; nt < 16; nt++) {
            acc[nt][0] *= f0; acc[nt][1] *= f0;
            acc[nt][2] *= f1; acc[nt][3] *= f1;
        }
        __syncwarp();

#pragma unroll
        for (int k2 = 0; k2 < 4; k2++) {
            uint32_t a[4];
            a[0] = Ps[(w * 16 + g) * PLD + k2 * 8 + tg];
            a[1] = Ps[(w * 16 + g + 8) * PLD + k2 * 8 + tg];
            a[2] = Ps[(w * 16 + g) * PLD + k2 * 8 + tg + 4];
            a[3] = Ps[(w * 16 + g + 8) * PLD + k2 * 8 + tg + 4];
#pragma unroll
            for (int nt = 0; nt < 16; nt++) {
                uint32_t bb[2];
                bb[0] = f2tf(Vc[(k2 * 8 + tg) * VLD + nt * 8 + g]);
                bb[1] = f2tf(Vc[(k2 * 8 + tg + 4) * VLD + nt * 8 + g]);
                mma_tf32(acc[nt], a, bb);
            }
        }
        __syncthreads();
    }

    const int h = kvh * 4 + w;
    const int baseA = ((b * 32 + h) * 16 + g) * NSPLIT + split;
    const int baseB = ((b * 32 + h) * 16 + g + 8) * NSPLIT + split;
    if (tg == 0) {
        g_pm[baseA] = m0; g_pl[baseA] = l0;
        g_pm[baseB] = m1; g_pl[baseB] = l1;
    }
#pragma unroll
    for (int nt = 0; nt < 16; nt++) {
        int col = nt * 8 + tg * 2;
        g_pacc[baseA * 128 + col]     = acc[nt][0];
        g_pacc[baseA * 128 + col + 1] = acc[nt][1];
        g_pacc[baseB * 128 + col]     = acc[nt][2];
        g_pacc[baseB * 128 + col + 1] = acc[nt][3];
    }
}

// ============================================================
// combine v2: two warps per row (splits 0-4 / 5-8), smem merge.
// Doubles load parallelism: 2048 -> 4096 warps.
// ============================================================
__global__ __launch_bounds__(256) void combine_kernel() {
    __shared__ float smm[4][2], smL[4][2];
    __shared__ float4 smo[4][32];
    const int wid = threadIdx.x >> 5, lane = threadIdx.x & 31;
    const int rl = wid >> 1, half = wid & 1;
    const int bhs = blockIdx.x * 4 + rl;
    const int base = bhs * NSPLIT;
    const int s0 = half ? 5 : 0, s1 = half ? 9 : 5;

    float m = -1e30f;
#pragma unroll
    for (int i = 0; i < 5; i++) {
        int s = s0 + i;
        if (s < s1) m = fmaxf(m, g_pm[base + s]);
    }
    float L = 0.f;
    float4 o = make_float4(0.f, 0.f, 0.f, 0.f);
#pragma unroll
    for (int i = 0; i < 5; i++) {
        int s = s0 + i;
        if (s < s1) {
            float e = __expf(g_pm[base + s] - m);
            L += g_pl[base + s] * e;
            float4 v = *(const float4*)(g_pacc + (base + s) * 128 + lane * 4);
            o.x += v.x * e; o.y += v.y * e; o.z += v.z * e; o.w += v.w * e;
        }
    }
    if (lane == 0) { smm[rl][half] = m; smL[rl][half] = L; }
    if (half) smo[rl][lane] = o;
    __syncthreads();
    if (!half) {
        float mB = smm[rl][1], LB = smL[rl][1];
        float M = fmaxf(m, mB);
        float eA = __expf(m - M), eB = __expf(mB - M);
        float4 ob = smo[rl][lane];
        float inv = 1.f / (L * eA + LB * eB);
        float4 r;
        r.x = (o.x * eA + ob.x * eB) * inv;
        r.y = (o.y * eA + ob.y * eB) * inv;
        r.z = (o.z * eA + ob.z * eB) * inv;
        r.w = (o.w * eA + ob.w * eB) * inv;
        int b = bhs >> 9, h = (bhs >> 4) & 31, s = bhs & 15;
        *(float4*)(g_attn + (b * 16 + s) * 4096 + h * 128 + lane * 4) = r;
    }
}

// ============================================================
extern "C" void kernel_launch(void* const* d_in, const int* in_sizes, int n_in,
                              void* d_out, int out_size) {
    const float* x  = (const float*)d_in[0];
    const float* fc = (const float*)d_in[1];
    const float* fs = (const float*)d_in[2];
    const float* ck = (const float*)d_in[3];
    const float* cv = (const float*)d_in[4];
    const float* Wq = (const float*)d_in[5];
    const float* Wk = (const float*)d_in[6];
    const float* Wv = (const float*)d_in[7];
    const float* Wo = (const float*)d_in[8];
    float* out = (float*)d_out;

    cudaFuncSetAttribute((const void*)gemm_k<6144, false, KSPLIT1>, cudaFuncAttributeMaxDynamicSharedMemorySize, GEMM_SMEM);
    cudaFuncSetAttribute((const void*)gemm_k<4096, true, KSPLIT2>,  cudaFuncAttributeMaxDynamicSharedMemorySize, GEMM_SMEM);
    cudaFuncSetAttribute(attn_kernel, cudaFuncAttributeMaxDynamicSharedMemorySize, ATTN_SMEM);

    float* acc_ptr;
    cudaGetSymbolAddress((void**)&acc_ptr, g_acc);

    gemm_k<6144, false, KSPLIT1><<<dim3(48, KSPLIT1), 256, GEMM_SMEM>>>(x, Wq, Wk, Wv, acc_ptr);
    rope_kernel<<<384, 256>>>(fc, fs, (float4*)out);
    attn_kernel<<<dim3(NSPLIT, 8, 4), 128, ATTN_SMEM>>>(ck, cv);
    combine_kernel<<<512, 256>>>();
    gemm_k<4096, true, KSPLIT2><<<dim3(32, KSPLIT2), 256, GEMM_SMEM>>>(nullptr, Wo, nullptr, nullptr, out);
}